// round 2
// baseline (speedup 1.0000x reference)
#include <cuda_runtime.h>
#include <cuda_bf16.h>
#include <cstdint>

// Problem shapes (fixed by the dataset's setup_inputs)
constexpr int B = 16;
constexpr int S = 512;
constexpr int D = 768;     // span_dim
constexpr int E = 128;     // distance embedding dim
constexpr int T = 64;
constexpr int O = 64;
constexpr int P = T * O;            // 4096 pairs per batch
constexpr int OUT_D = 2 * D + E;    // 1664 floats per output row
constexpr int D4 = D / 4;           // 192 float4
constexpr int E4 = E / 4;           // 32 float4
constexpr int OUT_D4 = OUT_D / 4;   // 416 float4
constexpr int NBINS = 14;

// bucket = (# bins <= width) - 1; bins[0]=0 and width>=0,
// so bucket = sum_{i=1..13} (width >= bins[i]).
__constant__ int c_bins[NBINS] = {0, 1, 2, 3, 4, 5, 7, 8, 15, 16, 31, 32, 63, 64};

__global__ __launch_bounds__(192, 8)
void pair_rep_kernel(const float4* __restrict__ spans,      // [B,S,D/4]
                     const float4* __restrict__ dist_emb,   // [14,E/4]
                     const int2*   __restrict__ span_idx,   // [S]
                     const int*    __restrict__ tgt,        // [B,T]
                     const int*    __restrict__ opi,        // [B,O]
                     float4*       __restrict__ out)        // [B*P, OUT_D/4]
{
    __shared__ float4 s_dist[NBINS * E4];   // 14*32 float4 = 7168 B
    __shared__ int    s_oi[O];
    __shared__ int    s_doff[O];

    const int tid = threadIdx.x;            // 0..191
    const int bt  = blockIdx.x;             // 0..1023
    const int b   = bt >> 6;
    const int t   = bt & (T - 1);

    // Stage full dist_emb table into smem (448 float4 across 192 threads)
    for (int i = tid; i < NBINS * E4; i += 192)
        s_dist[i] = __ldg(&dist_emb[i]);

    const int  ti = __ldg(&tgt[b * T + t]);
    const int2 ab = __ldg(&span_idx[ti]);

    // Precompute opinion index + bucket offset for all 64 opinions of this batch
    if (tid < O) {
        const int  oi = __ldg(&opi[b * O + tid]);
        const int2 cd = __ldg(&span_idx[oi]);
        const int  w  = min(abs(ab.y - cd.x), abs(ab.x - cd.y));
        int bucket = 0;
#pragma unroll
        for (int i = 1; i < NBINS; ++i)
            bucket += (w >= c_bins[i]) ? 1 : 0;
        s_oi[tid]   = oi;
        s_doff[tid] = bucket * E4;
    }

    // This thread's float4 of the target span — held in registers for all 64 rows
    const float4 vt = __ldg(&spans[(size_t)(b * S + ti) * D4 + tid]);

    __syncthreads();

    const float4* sp_b = spans + (size_t)b * S * D4;
    float4* dst = out + ((size_t)b * P + (size_t)t * O) * OUT_D4;

    // Software-pipelined loop over opinions: prefetch next span_o while storing current
    float4 vo = __ldg(&sp_b[(size_t)s_oi[0] * D4 + tid]);

#pragma unroll 1
    for (int o = 0; o < O; ++o) {
        const float4 cur = vo;
        if (o < O - 1)
            vo = __ldg(&sp_b[(size_t)s_oi[o + 1] * D4 + tid]);

        __stcs(&dst[tid], vt);                 // span_t section
        __stcs(&dst[D4 + tid], cur);           // span_o section
        if (tid < E4)                          // distance embedding section
            __stcs(&dst[2 * D4 + tid], s_dist[s_doff[o] + tid]);

        dst += OUT_D4;
    }
}

extern "C" void kernel_launch(void* const* d_in, const int* in_sizes, int n_in,
                              void* d_out, int out_size)
{
    // metadata order: spans, dist_emb, span_indices, target_indices, opinion_indices
    const float4* spans    = (const float4*)d_in[0];
    const float4* dist_emb = (const float4*)d_in[1];
    const int2*   span_idx = (const int2*)  d_in[2];
    const int*    tgt      = (const int*)   d_in[3];
    const int*    opi      = (const int*)   d_in[4];
    float4*       out      = (float4*)d_out;

    dim3 grid(B * T);    // 1024 blocks, one per (batch, target)
    dim3 block(192);
    pair_rep_kernel<<<grid, block>>>(spans, dist_emb, span_idx, tgt, opi, out);
}

// round 3
// speedup vs baseline: 1.1874x; 1.1874x over previous
#include <cuda_runtime.h>
#include <cuda_bf16.h>
#include <cstdint>

// Problem shapes (fixed by the dataset's setup_inputs)
constexpr int B = 16;
constexpr int S = 512;
constexpr int D = 768;     // span_dim
constexpr int E = 128;     // distance embedding dim
constexpr int T = 64;
constexpr int O = 64;
constexpr int P = T * O;            // 4096 pairs per batch
constexpr int OUT_D = 2 * D + E;    // 1664 floats per output row
constexpr int D4 = D / 4;           // 192 float4
constexpr int E4 = E / 4;           // 32 float4
constexpr int OUT_D4 = OUT_D / 4;   // 416 float4
constexpr int NBINS = 14;

// bucket = (# bins <= width) - 1; bins[0]=0 and width>=0,
// so bucket = sum_{i=1..13} (width >= bins[i]).
__constant__ int c_bins[NBINS] = {0, 1, 2, 3, 4, 5, 7, 8, 15, 16, 31, 32, 63, 64};

__global__ __launch_bounds__(192, 10)
void pair_rep_kernel(const float4* __restrict__ spans,      // [B,S,D/4]
                     const float4* __restrict__ dist_emb,   // [14,E/4]
                     const int2*   __restrict__ span_idx,   // [S]
                     const int*    __restrict__ tgt,        // [B,T]
                     const int*    __restrict__ opi,        // [B,O]
                     float4*       __restrict__ out)        // [B*P, OUT_D/4]
{
    const int row = blockIdx.x;        // 0 .. B*P-1
    const int b = row >> 12;           // / 4096
    const int p = row & (P - 1);
    const int t = p >> 6;              // / 64
    const int o = p & (O - 1);

    const int ti = __ldg(&tgt[b * T + t]);
    const int oi = __ldg(&opi[b * O + o]);

    const int2 ab = __ldg(&span_idx[ti]);
    const int2 cd = __ldg(&span_idx[oi]);
    const int w = min(abs(ab.y - cd.x), abs(ab.x - cd.y));

    int bucket = 0;
#pragma unroll
    for (int i = 1; i < NBINS; ++i)
        bucket += (w >= c_bins[i]) ? 1 : 0;

    const float4* st = spans + (size_t)(b * S + ti) * D4;
    const float4* so = spans + (size_t)(b * S + oi) * D4;
    const float4* de = dist_emb + (size_t)bucket * E4;
    float4* dst = out + (size_t)row * OUT_D4;

    const int tid = threadIdx.x;       // blockDim.x == 192 == D4

    // Issue all independent loads first (MLP=3 per thread for tid<32)
    const float4 vt = __ldg(&st[tid]);
    const float4 vo = __ldg(&so[tid]);
    float4 vd;
    if (tid < E4) vd = __ldg(&de[tid]);

    // Streaming stores — keep L2 for span reads
    __stcs(&dst[tid], vt);
    __stcs(&dst[D4 + tid], vo);
    if (tid < E4) __stcs(&dst[2 * D4 + tid], vd);
}

extern "C" void kernel_launch(void* const* d_in, const int* in_sizes, int n_in,
                              void* d_out, int out_size)
{
    // metadata order: spans, dist_emb, span_indices, target_indices, opinion_indices
    const float4* spans    = (const float4*)d_in[0];
    const float4* dist_emb = (const float4*)d_in[1];
    const int2*   span_idx = (const int2*)  d_in[2];
    const int*    tgt      = (const int*)   d_in[3];
    const int*    opi      = (const int*)   d_in[4];
    float4*       out      = (float4*)d_out;

    dim3 grid(B * P);   // 65536 blocks, one per output row
    dim3 block(192);
    pair_rep_kernel<<<grid, block>>>(spans, dist_emb, span_idx, tgt, opi, out);
}

// round 4
// speedup vs baseline: 1.2580x; 1.0595x over previous
#include <cuda_runtime.h>
#include <cuda_bf16.h>
#include <cstdint>

// Problem shapes (fixed by the dataset's setup_inputs)
constexpr int B = 16;
constexpr int S = 512;
constexpr int D = 768;     // span_dim
constexpr int E = 128;     // distance embedding dim
constexpr int T = 64;
constexpr int O = 64;
constexpr int P = T * O;            // 4096 pairs per batch
constexpr int OUT_D = 2 * D + E;    // 1664 floats per output row
constexpr int D4 = D / 4;           // 192 float4
constexpr int E4 = E / 4;           // 32 float4
constexpr int OUT_D4 = OUT_D / 4;   // 416 float4
constexpr int NBINS = 14;

// bucket = (# bins <= width) - 1; bins[0]=0 and width>=0,
// so bucket = sum_{i=1..13} (width >= bins[i]).
__constant__ int c_bins[NBINS] = {0, 1, 2, 3, 4, 5, 7, 8, 15, 16, 31, 32, 63, 64};

__device__ __forceinline__ int bucketize(int w) {
    int bucket = 0;
#pragma unroll
    for (int i = 1; i < NBINS; ++i)
        bucket += (w >= c_bins[i]) ? 1 : 0;
    return bucket;
}

// One block handles 2 output rows: same target, opinions (2g, 2g+1).
__global__ __launch_bounds__(192, 10)
void pair_rep_kernel(const float4* __restrict__ spans,      // [B,S,D/4]
                     const float4* __restrict__ dist_emb,   // [14,E/4]
                     const int2*   __restrict__ span_idx,   // [S]
                     const int*    __restrict__ tgt,        // [B,T]
                     const int*    __restrict__ opi,        // [B,O]
                     float4*       __restrict__ out)        // [B*P, OUT_D/4]
{
    const int blk = blockIdx.x;            // 0 .. B*T*(O/2)-1
    const int b   = blk >> 11;             // / 2048
    const int r   = blk & 2047;
    const int t   = r >> 5;                // / 32
    const int g   = r & 31;                // opinion pair group
    const int o0  = 2 * g;

    const int ti  = __ldg(&tgt[b * T + t]);
    const int oiA = __ldg(&opi[b * O + o0]);
    const int oiB = __ldg(&opi[b * O + o0 + 1]);

    const int2 ab = __ldg(&span_idx[ti]);
    const int2 cdA = __ldg(&span_idx[oiA]);
    const int2 cdB = __ldg(&span_idx[oiB]);
    const int wA = min(abs(ab.y - cdA.x), abs(ab.x - cdA.y));
    const int wB = min(abs(ab.y - cdB.x), abs(ab.x - cdB.y));
    const int bkA = bucketize(wA);
    const int bkB = bucketize(wB);

    const int tid = threadIdx.x;           // 0..191 == D4

    const float4* spb = spans + (size_t)b * S * D4;

    // Hoist all independent loads (vt reused for both rows)
    const float4 vt  = __ldg(&spb[(size_t)ti  * D4 + tid]);
    const float4 voA = __ldg(&spb[(size_t)oiA * D4 + tid]);
    const float4 voB = __ldg(&spb[(size_t)oiB * D4 + tid]);
    float4 vdA, vdB;
    if (tid < E4) {
        vdA = __ldg(&dist_emb[(size_t)bkA * E4 + tid]);
        vdB = __ldg(&dist_emb[(size_t)bkB * E4 + tid]);
    }

    float4* dst = out + ((size_t)b * P + (size_t)t * O + o0) * OUT_D4;

    // Row A
    __stcs(&dst[tid], vt);
    __stcs(&dst[D4 + tid], voA);
    if (tid < E4) __stcs(&dst[2 * D4 + tid], vdA);
    // Row B
    __stcs(&dst[OUT_D4 + tid], vt);
    __stcs(&dst[OUT_D4 + D4 + tid], voB);
    if (tid < E4) __stcs(&dst[OUT_D4 + 2 * D4 + tid], vdB);
}

extern "C" void kernel_launch(void* const* d_in, const int* in_sizes, int n_in,
                              void* d_out, int out_size)
{
    // metadata order: spans, dist_emb, span_indices, target_indices, opinion_indices
    const float4* spans    = (const float4*)d_in[0];
    const float4* dist_emb = (const float4*)d_in[1];
    const int2*   span_idx = (const int2*)  d_in[2];
    const int*    tgt      = (const int*)   d_in[3];
    const int*    opi      = (const int*)   d_in[4];
    float4*       out      = (float4*)d_out;

    dim3 grid(B * T * (O / 2));   // 32768 blocks, two rows each
    dim3 block(192);
    pair_rep_kernel<<<grid, block>>>(spans, dist_emb, span_idx, tgt, opi, out);
}